// round 3
// baseline (speedup 1.0000x reference)
#include <cuda_runtime.h>
#include <math.h>
#include <float.h>

#define FS        16000.0f
#define N_FILT    80
#define FILT_DIM  251
#define HALF_K    125
#define L_IN      32000
#define L_OUT     (L_IN - FILT_DIM + 1)   // 31750
#define BATCH     32
#define NPAIR     63                       // k-pairs (k=0..125 folded, h'[125]=center/2)
#define TILE      192
#define THREADS   512
#define NTILE     ((L_OUT + TILE - 1) / TILE)   // 166

typedef unsigned long long u64;

// packed filter pairs, layout [f][kappa]: (h'[2kappa], h'[2kappa+1])
__device__ u64 g_pairs[N_FILT * NPAIR];

// ---------------------------------------------------------------------------
// packed f32x2 helpers
// ---------------------------------------------------------------------------
__device__ __forceinline__ u64 fma2(u64 a, u64 b, u64 c) {
    u64 d;
    asm("fma.rn.f32x2 %0, %1, %2, %3;" : "=l"(d) : "l"(a), "l"(b), "l"(c));
    return d;
}
__device__ __forceinline__ u64 add2(u64 a, u64 b) {
    u64 d;
    asm("add.rn.f32x2 %0, %1, %2;" : "=l"(d) : "l"(a), "l"(b));
    return d;
}

// ---------------------------------------------------------------------------
// Kernel 1: build folded+paired filters, mirroring the JAX reference numerics.
// ---------------------------------------------------------------------------
__global__ void build_filters_kernel(const float* __restrict__ norm_f1,
                                     const float* __restrict__ norm_f2,
                                     const float* __restrict__ amplitude)
{
    const int f = blockIdx.x;
    const int t = threadIdx.x;

    const float min_n = 50.0f / FS;
    float f1n = fabsf(norm_f1[f]) + min_n;
    float f2n = f1n + fabsf(norm_f2[f] - f1n) + min_n;
    float f1 = f1n * FS;
    float f2 = f2n * FS;
    float amp = fabsf(amplitude[f]);

    __shared__ float bp[HALF_K];
    __shared__ float red[128];
    __shared__ float hs[HALF_K + 1];

    const float TWO_PI = 6.283185307179586f;

    float v = -FLT_MAX;
    if (t < HALF_K) {
        float tr = (float)(t + 1) / FS;
        float a2 = TWO_PI * f2 * tr;
        float a1 = TWO_PI * f1 * tr;
        float s2 = (float)(sin((double)a2) / (double)a2);
        float s1 = (float)(sin((double)a1) / (double)a1);
        float bb = amp * (2.0f * f2 * s2 - 2.0f * f1 * s1);
        bp[t] = bb;
        v = bb;
    }
    float center = amp * (2.0f * f2 - 2.0f * f1);
    v = fmaxf(v, center);

    red[t] = v;
    __syncthreads();
    for (int s = 64; s > 0; s >>= 1) {
        if (t < s) red[t] = fmaxf(red[t], red[t + s]);
        __syncthreads();
    }
    float mx = red[0];

    // folded taps h'[k], k=0..125 (h'[125] = center/2 since s-formula doubles it)
    for (int k = t; k <= HALF_K; k += blockDim.x) {
        float hv;
        if (k < HALF_K) {
            double wj  = 0.54 - 0.46 * cos(2.0 * M_PI * (double)k / 250.0);
            double wjm = 0.54 - 0.46 * cos(2.0 * M_PI * (double)(250 - k) / 250.0);
            hv = (bp[HALF_K - 1 - k] / mx) * (float)(0.5 * (wj + wjm));
        } else {
            hv = 0.5f * (center / mx);
        }
        hs[k] = hv;
    }
    __syncthreads();

    for (int q = t; q < NPAIR; q += blockDim.x) {
        float2 pv = make_float2(hs[2 * q], hs[2 * q + 1]);
        g_pairs[f * NPAIR + q] = *(u64*)&pv;
    }
}

// ---------------------------------------------------------------------------
// Kernel 2: folded conv, k-pairs packed into f32x2 FMAs.
// Block: 512 thr = 16 warps (5 filters each), tile = 192 outputs, 1 batch.
// Lane: c = lane&15, p = lane>>4 (output parity). Thread owns outputs
// o_j = 12c + 2j + p (j=0..5).
// ---------------------------------------------------------------------------
struct SmemS {
    u64   XT[2][6][32];       // forward pairs, parity p, transposed mod 6
    u64   RT[2][6][32];       // mirror  pairs, parity p, transposed mod 6
    u64   gsh[16][63][6];     // per-warp filter pairs (5 used + pad), 16B aligned
    float xt[448];            // raw x tile
};
union SmemU {
    SmemS s;
    float outbuf[N_FILT * TILE];   // 61440 B
};

__global__ void __launch_bounds__(THREADS, 1)
sinc_conv_kernel(const float* __restrict__ x, float* __restrict__ out)
{
    extern __shared__ SmemU smem_u[];
    SmemU* SM = smem_u;

    const int b   = blockIdx.y;
    const int l0  = blockIdx.x * TILE;
    const int tid = threadIdx.x;
    const int w   = tid >> 5;
    const int lane = tid & 31;

    // ---- fill raw x tile (zero-padded) + per-warp filter pairs ----
    const float* xb = x + (size_t)b * L_IN;
    for (int t = tid; t < 444; t += THREADS) {
        int gi = l0 + t;
        SM->s.xt[t] = (gi < L_IN) ? xb[gi] : 0.0f;
    }
    for (int idx = tid; idx < 16 * 63 * 5; idx += THREADS) {
        int w2 = idx / 315, r2 = idx % 315;
        int kk = r2 / 5,    i  = r2 % 5;
        SM->s.gsh[w2][kk][i] = g_pairs[(5 * w2 + i) * NPAIR + kk];
    }
    __syncthreads();

    // ---- expand x into the 4 pair-aligned transposed arrays ----
    // XT[0][m%6][m/6] = (xt[2m],   xt[2m+1])      (even outputs, forward)
    // XT[1][...]      = (xt[2m+1], xt[2m+2])      (odd  outputs, forward)
    // RT[0][...]      = (xt[440-2m], xt[439-2m])  (even outputs, mirror)
    // RT[1][...]      = (xt[441-2m], xt[440-2m])  (odd  outputs, mirror)
    {
        const float* xt = SM->s.xt;
        for (int idx = tid; idx < 4 * 158; idx += THREADS) {
            int a = idx / 158, m = idx % 158;
            int row = m % 6, col = m / 6;
            float2 v;
            if      (a == 0) v = make_float2(xt[2 * m],       xt[2 * m + 1]);
            else if (a == 1) v = make_float2(xt[2 * m + 1],   xt[2 * m + 2]);
            else if (a == 2) v = make_float2(xt[440 - 2 * m], xt[439 - 2 * m]);
            else             v = make_float2(xt[441 - 2 * m], xt[440 - 2 * m]);
            u64 uv = *(u64*)&v;
            if (a < 2) SM->s.XT[a][row][col]     = uv;
            else       SM->s.RT[a - 2][row][col] = uv;
        }
    }
    __syncthreads();

    const int c  = lane & 15;
    const int p  = lane >> 4;
    const int cb = 15 - c;
    const u64 (*X)[32] = SM->s.XT[p];
    const u64 (*R)[32] = SM->s.RT[p];

    // register windows: A[i] <-> fwd pair t = kappa0 + i ; B[i] <-> mir pair u = kappa0 - 5 + i
    u64 A[8], B[8];
    #pragma unroll
    for (int i = 0; i < 6; i++) { A[i] = X[i][c]; B[i] = R[i][cb]; }
    A[6] = X[0][c + 1];  A[7] = X[1][c + 1];
    B[6] = R[0][cb + 1]; B[7] = R[1][cb + 1];

    u64 acc[5][6];
    #pragma unroll
    for (int i = 0; i < 5; i++)
        #pragma unroll
        for (int j = 0; j < 6; j++)
            acc[i][j] = 0ull;

#define STEP(e, KOFF) do {                                                    \
    const u64* gk = &SM->s.gsh[w][(KOFF)][0];                                 \
    ulonglong2 G01 = *(const ulonglong2*)(gk);                                \
    ulonglong2 G23 = *(const ulonglong2*)(gk + 2);                            \
    u64 G4 = gk[4];                                                           \
    _Pragma("unroll")                                                         \
    for (int j = 0; j < 6; j++) {                                             \
        u64 s2 = add2(A[j + (e)], B[5 + (e) - j]);                            \
        acc[0][j] = fma2(G01.x, s2, acc[0][j]);                               \
        acc[1][j] = fma2(G01.y, s2, acc[1][j]);                               \
        acc[2][j] = fma2(G23.x, s2, acc[2][j]);                               \
        acc[3][j] = fma2(G23.y, s2, acc[3][j]);                               \
        acc[4][j] = fma2(G4,    s2, acc[4][j]);                               \
    }                                                                         \
} while (0)

    #pragma unroll 1
    for (int d = 0; d < 10; d++) {
        const int k0 = 6 * d;
        STEP(0, k0); STEP(1, k0 + 1); STEP(2, k0 + 2);
        {
            #pragma unroll
            for (int i = 0; i < 5; i++) { A[i] = A[i + 3]; B[i] = B[i + 3]; }
            int ca  = c  + d + 1;
            int cbn = cb + d + 1;
            A[5] = X[2][ca];  A[6] = X[3][ca];  A[7] = X[4][ca];
            B[5] = R[2][cbn]; B[6] = R[3][cbn]; B[7] = R[4][cbn];
        }
        STEP(0, k0 + 3); STEP(1, k0 + 4); STEP(2, k0 + 5);
        {
            #pragma unroll
            for (int i = 0; i < 5; i++) { A[i] = A[i + 3]; B[i] = B[i + 3]; }
            int ca  = c  + d + 1;
            int cbn = cb + d + 1;
            A[5] = X[5][ca];  A[6] = X[0][ca + 1];  A[7] = X[1][ca + 1];
            B[5] = R[5][cbn]; B[6] = R[0][cbn + 1]; B[7] = R[1][cbn + 1];
        }
    }
    // tail: kappa = 60, 61, 62
    STEP(0, 60); STEP(1, 61); STEP(2, 62);
#undef STEP

    // ---- epilogue: horizontal add, stage to smem, coalesced store ----
    __syncthreads();   // all XT/gsh reads done before union reuse
    const int fbase = 5 * w;
    #pragma unroll
    for (int i = 0; i < 5; i++)
        #pragma unroll
        for (int j = 0; j < 6; j++) {
            float2 v = *(float2*)&acc[i][j];
            SM->outbuf[(fbase + i) * TILE + 12 * c + 2 * j + p] = v.x + v.y;
        }
    __syncthreads();

    for (int idx = tid; idx < N_FILT * (TILE / 2); idx += THREADS) {
        int f = idx / (TILE / 2), q = idx % (TILE / 2);
        int l = l0 + 2 * q;
        if (l < L_OUT) {
            float2 v = make_float2(SM->outbuf[f * TILE + 2 * q],
                                   SM->outbuf[f * TILE + 2 * q + 1]);
            *(float2*)(out + ((size_t)b * N_FILT + f) * L_OUT + l) = v;
        }
    }
}

// ---------------------------------------------------------------------------
extern "C" void kernel_launch(void* const* d_in, const int* in_sizes, int n_in,
                              void* d_out, int out_size)
{
    const float* x       = (const float*)d_in[0];
    const float* norm_f1 = (const float*)d_in[1];
    const float* norm_f2 = (const float*)d_in[2];
    const float* ampl    = (const float*)d_in[3];
    float* out = (float*)d_out;

    static int smem_set = 0;
    (void)smem_set;
    cudaFuncSetAttribute(sinc_conv_kernel,
                         cudaFuncAttributeMaxDynamicSharedMemorySize,
                         (int)sizeof(SmemU));

    build_filters_kernel<<<N_FILT, 128>>>(norm_f1, norm_f2, ampl);

    dim3 grid(NTILE, BATCH);   // (166, 32)
    sinc_conv_kernel<<<grid, THREADS, sizeof(SmemU)>>>(x, out);
}

// round 4
// speedup vs baseline: 1.0243x; 1.0243x over previous
#include <cuda_runtime.h>
#include <math.h>
#include <float.h>

#define FS        16000.0f
#define N_FILT    80
#define FILT_DIM  251
#define HALF_K    125
#define L_IN      32000
#define L_OUT     (L_IN - FILT_DIM + 1)   // 31750
#define BATCH     32

#define THREADS   256
#define NWARP     8
#define FPW       10                      // filters per warp
#define TILE      256                     // outputs per block (32 lanes x 8)
#define NTILE     ((L_OUT + TILE - 1) / TILE)   // 125
#define COLS      136                     // used columns per lane row
#define CSTRIDE   140                     // row stride (mod 32 = 12 -> conflict-free float4)

// folded filter taps h'[k], layout [k][f]; h'[125] = center/2 (s doubles it)
__device__ float g_filt[(HALF_K + 1) * N_FILT];

// ---------------------------------------------------------------------------
// Kernel 1: build folded filters, mirroring the JAX reference numerics.
// ---------------------------------------------------------------------------
__global__ void build_filters_kernel(const float* __restrict__ norm_f1,
                                     const float* __restrict__ norm_f2,
                                     const float* __restrict__ amplitude)
{
    const int f = blockIdx.x;
    const int t = threadIdx.x;

    const float min_n = 50.0f / FS;
    float f1n = fabsf(norm_f1[f]) + min_n;
    float f2n = f1n + fabsf(norm_f2[f] - f1n) + min_n;
    float f1 = f1n * FS;
    float f2 = f2n * FS;
    float amp = fabsf(amplitude[f]);

    __shared__ float bp[HALF_K];
    __shared__ float red[128];

    const float TWO_PI = 6.283185307179586f;

    float v = -FLT_MAX;
    if (t < HALF_K) {
        float tr = (float)(t + 1) / FS;          // exact integers 1..125 / fs
        float a2 = TWO_PI * f2 * tr;             // fp32 arg like reference
        float a1 = TWO_PI * f1 * tr;
        float s2 = (float)(sin((double)a2) / (double)a2);
        float s1 = (float)(sin((double)a1) / (double)a1);
        float bb = amp * (2.0f * f2 * s2 - 2.0f * f1 * s1);
        bp[t] = bb;
        v = bb;
    }
    float center = amp * (2.0f * f2 - 2.0f * f1);
    v = fmaxf(v, center);

    red[t] = v;
    __syncthreads();
    for (int s = 64; s > 0; s >>= 1) {
        if (t < s) red[t] = fmaxf(red[t], red[t + s]);
        __syncthreads();
    }
    float mx = red[0];

    for (int k = t; k <= HALF_K; k += blockDim.x) {
        float hv;
        if (k < HALF_K) {
            double wj  = 0.54 - 0.46 * cos(2.0 * M_PI * (double)k / 250.0);
            double wjm = 0.54 - 0.46 * cos(2.0 * M_PI * (double)(250 - k) / 250.0);
            hv = (bp[HALF_K - 1 - k] / mx) * (float)(0.5 * (wj + wjm));
        } else {
            hv = 0.5f * (center / mx);   // folded center tap
        }
        g_filt[k * N_FILT + f] = hv;
    }
}

// ---------------------------------------------------------------------------
// Kernel 2: folded symmetric conv.
// Block: 256 thr = 8 warps; warp w owns filters [10w, 10w+10); lane tl owns
// 8 consecutive outputs l = l0 + 8*tl + j. Per-lane private x rows in smem
// (forward + mirrored) make all sliding-window float4 LDS conflict-free.
// ---------------------------------------------------------------------------
struct Smem {
    float gsh[HALF_K + 1][NWARP][12];   // per-warp taps, 10 used + 2 pad (48B rows)
    float xsl[32][CSTRIDE];             // xsl[tl][t] = x[l0 + 8*tl + t]
    float msl[32][CSTRIDE];             // msl[tl][t] = x[l0 + 8*tl + 257 - t]
};

__global__ void __launch_bounds__(THREADS, 2)
sinc_conv_kernel(const float* __restrict__ x, float* __restrict__ out)
{
    extern __shared__ Smem sm[];
    Smem* S = sm;

    const int b   = blockIdx.y;
    const int l0  = blockIdx.x * TILE;
    const int tid = threadIdx.x;
    const int w   = tid >> 5;
    const int tl  = tid & 31;

    // ---- stage filter taps: gsh[k][w][i] = g_filt[k*80 + 10w + i] ----
    for (int idx = tid; idx < (HALF_K + 1) * N_FILT; idx += THREADS) {
        int k = idx / N_FILT, f = idx % N_FILT;
        S->gsh[k][f / FPW][f % FPW] = g_filt[idx];
    }
    // ---- stage per-lane x rows (forward + mirror), zero-padded ----
    const float* xb = x + (size_t)b * L_IN;
    for (int idx = tid; idx < 32 * COLS; idx += THREADS) {
        int row = idx / COLS, col = idx % COLS;
        int gf = l0 + 8 * row + col;
        S->xsl[row][col] = (gf < L_IN) ? xb[gf] : 0.0f;
        int gm = l0 + 8 * row + 257 - col;      // always >= 122
        S->msl[row][col] = (gm < L_IN) ? xb[gm] : 0.0f;
    }
    __syncthreads();

    const float* xrow = &S->xsl[tl][0];
    const float* mrow = &S->msl[tl][0];

    // register windows over [k0, k0+11]
    float r[12], m[12];
    #pragma unroll
    for (int q = 0; q < 3; q++) {
        float4 v = *(const float4*)(xrow + 4 * q);
        r[4*q] = v.x; r[4*q+1] = v.y; r[4*q+2] = v.z; r[4*q+3] = v.w;
        float4 u = *(const float4*)(mrow + 4 * q);
        m[4*q] = u.x; m[4*q+1] = u.y; m[4*q+2] = u.z; m[4*q+3] = u.w;
    }

    float acc[FPW][8];
    #pragma unroll
    for (int i = 0; i < FPW; i++)
        #pragma unroll
        for (int j = 0; j < 8; j++)
            acc[i][j] = 0.0f;

#define KSTEP(K, KK) do {                                                     \
    const float* gk = &S->gsh[(K)][w][0];                                     \
    float4 g0 = *(const float4*)gk;                                           \
    float4 g1 = *(const float4*)(gk + 4);                                     \
    float2 g2 = *(const float2*)(gk + 8);                                     \
    _Pragma("unroll")                                                         \
    for (int j = 0; j < 8; j++) {                                             \
        float s = r[(KK) + j] + m[7 + (KK) - j];                              \
        acc[0][j] = fmaf(g0.x, s, acc[0][j]);                                 \
        acc[1][j] = fmaf(g0.y, s, acc[1][j]);                                 \
        acc[2][j] = fmaf(g0.z, s, acc[2][j]);                                 \
        acc[3][j] = fmaf(g0.w, s, acc[3][j]);                                 \
        acc[4][j] = fmaf(g1.x, s, acc[4][j]);                                 \
        acc[5][j] = fmaf(g1.y, s, acc[5][j]);                                 \
        acc[6][j] = fmaf(g1.z, s, acc[6][j]);                                 \
        acc[7][j] = fmaf(g1.w, s, acc[7][j]);                                 \
        acc[8][j] = fmaf(g2.x, s, acc[8][j]);                                 \
        acc[9][j] = fmaf(g2.y, s, acc[9][j]);                                 \
    }                                                                         \
} while (0)

    // 31 groups of 4 taps (k = 0..123), sliding windows by 4
    #pragma unroll 1
    for (int d = 0; d < 31; d++) {
        const int k0 = 4 * d;
        KSTEP(k0 + 0, 0);
        KSTEP(k0 + 1, 1);
        KSTEP(k0 + 2, 2);
        KSTEP(k0 + 3, 3);
        // slide by 4 (next k0 = 4d+4; need cols [4d+4 .. 4d+15])
        #pragma unroll
        for (int t = 0; t < 8; t++) { r[t] = r[t + 4]; m[t] = m[t + 4]; }
        float4 v = *(const float4*)(xrow + k0 + 12);
        r[8] = v.x; r[9] = v.y; r[10] = v.z; r[11] = v.w;
        float4 u = *(const float4*)(mrow + k0 + 12);
        m[8] = u.x; m[9] = u.y; m[10] = u.z; m[11] = u.w;
    }
    // tail: k = 124, 125 (windows at k0 = 124)
    KSTEP(124, 0);
    KSTEP(125, 1);
#undef KSTEP

    // ---- store: 8 consecutive outputs per filter per thread ----
    const int ob0 = l0 + 8 * tl;
    const bool full = (l0 + TILE) <= L_OUT;
    #pragma unroll
    for (int i = 0; i < FPW; i++) {
        float* op = out + ((size_t)b * N_FILT + w * FPW + i) * L_OUT + ob0;
        if (full) {
            #pragma unroll
            for (int j = 0; j < 4; j++)
                *(float2*)(op + 2 * j) = make_float2(acc[i][2*j], acc[i][2*j+1]);
        } else {
            #pragma unroll
            for (int j = 0; j < 8; j++)
                if (ob0 + j < L_OUT) op[j] = acc[i][j];
        }
    }
}

// ---------------------------------------------------------------------------
extern "C" void kernel_launch(void* const* d_in, const int* in_sizes, int n_in,
                              void* d_out, int out_size)
{
    const float* x       = (const float*)d_in[0];
    const float* norm_f1 = (const float*)d_in[1];
    const float* norm_f2 = (const float*)d_in[2];
    const float* ampl    = (const float*)d_in[3];
    float* out = (float*)d_out;

    cudaFuncSetAttribute(sinc_conv_kernel,
                         cudaFuncAttributeMaxDynamicSharedMemorySize,
                         (int)sizeof(Smem));

    build_filters_kernel<<<N_FILT, 128>>>(norm_f1, norm_f2, ampl);

    dim3 grid(NTILE, BATCH);   // (125, 32)
    sinc_conv_kernel<<<grid, THREADS, sizeof(Smem)>>>(x, out);
}

// round 5
// speedup vs baseline: 1.0945x; 1.0685x over previous
#include <cuda_runtime.h>
#include <math.h>
#include <float.h>

#define FS        16000.0f
#define N_FILT    80
#define FILT_DIM  251
#define HALF_K    125
#define L_IN      32000
#define L_OUT     (L_IN - FILT_DIM + 1)   // 31750
#define BATCH     32

#define THREADS   512
#define NWARP     16
#define FPW       5                        // filters per warp
#define TILE      256                      // outputs per block
#define NTILE     ((L_OUT + TILE - 1) / TILE)   // 125
#define COLS      136                      // used columns per lane row
#define CSTRIDE   140                      // 140 % 32 == 12 -> conflict-free float4

// folded filter taps h'[k], layout [k][f]; h'[125] = center/2 (s doubles it)
__device__ float g_filt[(HALF_K + 1) * N_FILT];

// ---------------------------------------------------------------------------
// Kernel 1: build folded filters, mirroring the JAX reference numerics.
// ---------------------------------------------------------------------------
__global__ void build_filters_kernel(const float* __restrict__ norm_f1,
                                     const float* __restrict__ norm_f2,
                                     const float* __restrict__ amplitude)
{
    const int f = blockIdx.x;
    const int t = threadIdx.x;

    const float min_n = 50.0f / FS;
    float f1n = fabsf(norm_f1[f]) + min_n;
    float f2n = f1n + fabsf(norm_f2[f] - f1n) + min_n;
    float f1 = f1n * FS;
    float f2 = f2n * FS;
    float amp = fabsf(amplitude[f]);

    __shared__ float bp[HALF_K];
    __shared__ float red[128];

    const float TWO_PI = 6.283185307179586f;

    float v = -FLT_MAX;
    if (t < HALF_K) {
        float tr = (float)(t + 1) / FS;          // exact integers 1..125 / fs
        float a2 = TWO_PI * f2 * tr;             // fp32 arg like reference
        float a1 = TWO_PI * f1 * tr;
        float s2 = (float)(sin((double)a2) / (double)a2);
        float s1 = (float)(sin((double)a1) / (double)a1);
        float bb = amp * (2.0f * f2 * s2 - 2.0f * f1 * s1);
        bp[t] = bb;
        v = bb;
    }
    float center = amp * (2.0f * f2 - 2.0f * f1);
    v = fmaxf(v, center);

    red[t] = v;
    __syncthreads();
    for (int s = 64; s > 0; s >>= 1) {
        if (t < s) red[t] = fmaxf(red[t], red[t + s]);
        __syncthreads();
    }
    float mx = red[0];

    for (int k = t; k <= HALF_K; k += blockDim.x) {
        float hv;
        if (k < HALF_K) {
            double wj  = 0.54 - 0.46 * cos(2.0 * M_PI * (double)k / 250.0);
            double wjm = 0.54 - 0.46 * cos(2.0 * M_PI * (double)(250 - k) / 250.0);
            hv = (bp[HALF_K - 1 - k] / mx) * (float)(0.5 * (wj + wjm));
        } else {
            hv = 0.5f * (center / mx);   // folded center tap
        }
        g_filt[k * N_FILT + f] = hv;
    }
}

// ---------------------------------------------------------------------------
// Kernel 2: folded symmetric conv, ring-buffer register windows.
// 512 thr = 16 warps; warp w owns filters [5w,5w+5); lane tl owns 8
// consecutive outputs l = l0 + 8*tl + j.
//   xsl[tl][t] = x[l0 + 8*tl + t]        (forward)
//   msl[tl][t] = x[l0 + 8*tl + 257 - t]  (mirror; term for (k,j) is msl[k+7-j])
// Row stride 140 (mod 32 = 12) -> all float4 window reloads conflict-free.
// ---------------------------------------------------------------------------
struct Smem {
    float gsh[HALF_K + 1][NWARP][8];    // taps: 5 used + 3 pad (32B per warp row)
    float xsl[32][CSTRIDE];
    float msl[32][CSTRIDE];
};

__global__ void __launch_bounds__(THREADS, 1)
sinc_conv_kernel(const float* __restrict__ x, float* __restrict__ out)
{
    extern __shared__ Smem sm[];
    Smem* S = sm;

    const int b   = blockIdx.y;
    const int l0  = blockIdx.x * TILE;
    const int tid = threadIdx.x;
    const int w   = tid >> 5;
    const int tl  = tid & 31;

    // ---- stage taps: gsh[k][f/5][f%5] ----
    for (int idx = tid; idx < (HALF_K + 1) * N_FILT; idx += THREADS) {
        int k = idx / N_FILT, f = idx % N_FILT;
        S->gsh[k][f / FPW][f % FPW] = g_filt[idx];
    }
    // ---- stage per-lane rows (forward + mirror), zero-padded ----
    const float* xb = x + (size_t)b * L_IN;
    for (int idx = tid; idx < 32 * COLS; idx += THREADS) {
        int row = idx / COLS, col = idx % COLS;
        int gf = l0 + 8 * row + col;
        S->xsl[row][col] = (gf < L_IN) ? xb[gf] : 0.0f;
        int gm = l0 + 8 * row + 257 - col;    // >= l0 + 121, < L_IN except last tiles
        S->msl[row][col] = (gm < L_IN) ? xb[gm] : 0.0f;
    }
    __syncthreads();

    const float* xrow = &S->xsl[tl][0];
    const float* mrow = &S->msl[tl][0];

    // ring windows: slot(t) = t % 12 holds xsl/msl column t of current window
    float r[12], m[12];
    #pragma unroll
    for (int q = 0; q < 3; q++) {
        float4 v = *(const float4*)(xrow + 4 * q);
        r[4*q] = v.x; r[4*q+1] = v.y; r[4*q+2] = v.z; r[4*q+3] = v.w;
        float4 u = *(const float4*)(mrow + 4 * q);
        m[4*q] = u.x; m[4*q+1] = u.y; m[4*q+2] = u.z; m[4*q+3] = u.w;
    }

    float acc[FPW][8];
    #pragma unroll
    for (int i = 0; i < FPW; i++)
        #pragma unroll
        for (int j = 0; j < 8; j++)
            acc[i][j] = 0.0f;

    // process NK taps starting at tap KB, ring offset OFF (compile-time)
#define PHASE(OFF, KB, NK) do {                                               \
    _Pragma("unroll")                                                         \
    for (int kk = 0; kk < (NK); kk++) {                                       \
        const float* gk = &S->gsh[(KB) + kk][w][0];                           \
        float4 g0 = *(const float4*)gk;                                       \
        float  g4 = gk[4];                                                    \
        _Pragma("unroll")                                                     \
        for (int j = 0; j < 8; j++) {                                         \
            float s = r[((OFF) + kk + j) % 12] + m[((OFF) + 7 + kk - j) % 12];\
            acc[0][j] = fmaf(g0.x, s, acc[0][j]);                             \
            acc[1][j] = fmaf(g0.y, s, acc[1][j]);                             \
            acc[2][j] = fmaf(g0.z, s, acc[2][j]);                             \
            acc[3][j] = fmaf(g0.w, s, acc[3][j]);                             \
            acc[4][j] = fmaf(g4,   s, acc[4][j]);                             \
        }                                                                     \
    }                                                                         \
} while (0)

    // reload retired slots [SLOT..SLOT+3] from column COL (compile-time SLOT)
#define RELOAD(SLOT, COL) do {                                                \
    float4 v = *(const float4*)(xrow + (COL));                                \
    r[(SLOT)+0] = v.x; r[(SLOT)+1] = v.y; r[(SLOT)+2] = v.z; r[(SLOT)+3] = v.w;\
    float4 u = *(const float4*)(mrow + (COL));                                \
    m[(SLOT)+0] = u.x; m[(SLOT)+1] = u.y; m[(SLOT)+2] = u.z; m[(SLOT)+3] = u.w;\
} while (0)

    #pragma unroll 1
    for (int d = 0; d < 10; d++) {
        const int k0 = 12 * d;
        PHASE(0, k0 + 0, 4);  RELOAD(0, k0 + 12);
        PHASE(4, k0 + 4, 4);  RELOAD(4, k0 + 16);
        PHASE(8, k0 + 8, 4);  RELOAD(8, k0 + 20);
    }
    // tail: k = 120..125 (window t in [120,131], slot = t % 12, 120 % 12 == 0)
    PHASE(0, 120, 4);  RELOAD(0, 132);
    PHASE(4, 124, 2);
#undef PHASE
#undef RELOAD

    // ---- store: 8 consecutive outputs per filter per thread ----
    const int ob0 = l0 + 8 * tl;
    const bool full = (l0 + TILE) <= L_OUT;
    #pragma unroll
    for (int i = 0; i < FPW; i++) {
        float* op = out + ((size_t)b * N_FILT + w * FPW + i) * L_OUT + ob0;
        if (full) {
            #pragma unroll
            for (int j = 0; j < 4; j++)
                *(float2*)(op + 2 * j) = make_float2(acc[i][2*j], acc[i][2*j+1]);
        } else {
            #pragma unroll
            for (int j = 0; j < 8; j++)
                if (ob0 + j < L_OUT) op[j] = acc[i][j];
        }
    }
}

// ---------------------------------------------------------------------------
extern "C" void kernel_launch(void* const* d_in, const int* in_sizes, int n_in,
                              void* d_out, int out_size)
{
    const float* x       = (const float*)d_in[0];
    const float* norm_f1 = (const float*)d_in[1];
    const float* norm_f2 = (const float*)d_in[2];
    const float* ampl    = (const float*)d_in[3];
    float* out = (float*)d_out;

    cudaFuncSetAttribute(sinc_conv_kernel,
                         cudaFuncAttributeMaxDynamicSharedMemorySize,
                         (int)sizeof(Smem));

    build_filters_kernel<<<N_FILT, 128>>>(norm_f1, norm_f2, ampl);

    dim3 grid(NTILE, BATCH);   // (125, 32)
    sinc_conv_kernel<<<grid, THREADS, sizeof(Smem)>>>(x, out);
}

// round 7
// speedup vs baseline: 2.2876x; 2.0901x over previous
#include <cuda_runtime.h>
#include <cuda_bf16.h>
#include <math.h>
#include <float.h>
#include <stdint.h>

#define FS        16000.0f
#define N_FILT    80
#define FILT_DIM  251
#define HALF_K    125
#define L_IN      32000
#define L_OUT     (L_IN - FILT_DIM + 1)   // 31750
#define BATCH     32

#define KPAD      256
#define KSTEPS    16                       // KPAD / 16
#define NT        10                       // 80 / 8 n-tiles
#define MTILE     256                      // l's per CTA (8 warps x 32)
#define NLT       ((L_OUT + MTILE - 1) / MTILE)   // 125
#define THREADS   256

// H in fragment-linear layout: [split][kstep][ntile][lane] -> uint2 {b0,b1}
// b0 = (H[f][k0+2q], H[f][k0+2q+1]), b1 = same at k+8; f = ntile*8 + (lane>>2), q = lane&3
__device__ __align__(16) uint2 Hfrag_g[2][KSTEPS][NT][32];

struct Smem {
    uint2    Hf[2][KSTEPS][NT][32];   // 81920 B
    uint32_t xeh[264];                // (bf16 x[2j], x[2j+1]) hi
    uint32_t xoh[264];                // (bf16 x[2j+1], x[2j+2]) hi
    uint32_t xel[264];                // lo splits
    uint32_t xol[264];
};

// ---------------------------------------------------------------------------
__device__ __forceinline__ uint32_t pack_bf2(__nv_bfloat16 a, __nv_bfloat16 b) {
    __nv_bfloat162 t; t.x = a; t.y = b;
    return *(uint32_t*)&t;
}

__device__ __forceinline__ void mma16816(float d[4],
                                         uint32_t a0, uint32_t a1,
                                         uint32_t a2, uint32_t a3,
                                         uint32_t b0, uint32_t b1) {
    asm volatile(
        "mma.sync.aligned.m16n8k16.row.col.f32.bf16.bf16.f32 "
        "{%0,%1,%2,%3}, {%4,%5,%6,%7}, {%8,%9}, {%0,%1,%2,%3};"
        : "+f"(d[0]), "+f"(d[1]), "+f"(d[2]), "+f"(d[3])
        : "r"(a0), "r"(a1), "r"(a2), "r"(a3), "r"(b0), "r"(b1));
}

// ---------------------------------------------------------------------------
// Kernel 1: build taps with reference numerics, write bf16 hi/lo splits
// directly in fragment-linear layout.
// ---------------------------------------------------------------------------
__global__ void build_filters_kernel(const float* __restrict__ norm_f1,
                                     const float* __restrict__ norm_f2,
                                     const float* __restrict__ amplitude)
{
    const int f = blockIdx.x;
    const int t = threadIdx.x;

    const float min_n = 50.0f / FS;
    float f1n = fabsf(norm_f1[f]) + min_n;
    float f2n = f1n + fabsf(norm_f2[f] - f1n) + min_n;
    float f1 = f1n * FS;
    float f2 = f2n * FS;
    float amp = fabsf(amplitude[f]);

    __shared__ float bp[HALF_K];
    __shared__ float red[128];

    const float TWO_PI = 6.283185307179586f;

    float v = -FLT_MAX;
    if (t < HALF_K) {
        float tr = (float)(t + 1) / FS;          // exact integers 1..125 / fs
        float a2 = TWO_PI * f2 * tr;             // fp32 arg like reference
        float a1 = TWO_PI * f1 * tr;
        float s2 = (float)(sin((double)a2) / (double)a2);
        float s1 = (float)(sin((double)a1) / (double)a1);
        float bb = amp * (2.0f * f2 * s2 - 2.0f * f1 * s1);
        bp[t] = bb;
        v = bb;
    }
    float center = amp * (2.0f * f2 - 2.0f * f1);
    v = fmaxf(v, center);

    red[t] = v;
    __syncthreads();
    for (int s = 64; s > 0; s >>= 1) {
        if (t < s) red[t] = fmaxf(red[t], red[t + s]);
        __syncthreads();
    }
    float mx = red[0];

    const int nt   = f >> 3;
    const int lrow = f & 7;

    for (int k = t; k < KPAD; k += blockDim.x) {
        float hv = 0.0f;
        if (k < FILT_DIM) {
            float bpv = (k < HALF_K) ? bp[HALF_K - 1 - k]
                       : (k == HALF_K ? center : bp[k - HALF_K - 1]);
            double wj = 0.54 - 0.46 * cos(2.0 * M_PI * (double)k / 250.0);
            hv = (bpv / mx) * (float)wj;
        }
        __nv_bfloat16 hi = __float2bfloat16(hv);
        __nv_bfloat16 lo = __float2bfloat16(hv - __bfloat162float(hi));

        int ks = k >> 4, kk = k & 15;
        int bsel = kk >> 3;            // b0 / b1
        int q    = (kk >> 1) & 3;      // thread-in-group
        int e    = kk & 1;             // element within b32
        int lane = lrow * 4 + q;

        ((__nv_bfloat16*)&Hfrag_g[0][ks][nt][lane])[bsel * 2 + e] = hi;
        ((__nv_bfloat16*)&Hfrag_g[1][ks][nt][lane])[bsel * 2 + e] = lo;
    }
}

// ---------------------------------------------------------------------------
// Kernel 2: implicit-GEMM conv via mma.sync m16n8k16 bf16 (3-pass split).
// CTA: 1 batch x 256 l x 80 f. Warp w owns l = [32w, 32w+32) (2 m-tiles).
// Toeplitz A-fragments: a1 == a2, and fragments need only 3 b32 loads from
// parity-split bf16 pair arrays.
// ---------------------------------------------------------------------------
__global__ void __launch_bounds__(THREADS, 2)
sinc_conv_kernel(const float* __restrict__ x, float* __restrict__ out)
{
    extern __shared__ __align__(16) char smem_raw[];
    Smem* S = (Smem*)smem_raw;

    const int b    = blockIdx.y;
    const int l0   = blockIdx.x * MTILE;
    const int tid  = threadIdx.x;
    const int w    = tid >> 5;
    const int lane = tid & 31;

    // ---- stage H fragments (80 KB, L2-hot) ----
    {
        const uint4* src = (const uint4*)Hfrag_g;
        uint4* dst = (uint4*)S->Hf;
        #pragma unroll 5
        for (int i = tid; i < 5120; i += THREADS) dst[i] = src[i];
    }
    // ---- stage x pair-words (hi/lo x even/odd), zero-padded ----
    {
        const float* xb = x + (size_t)b * L_IN;
        for (int j = tid; j < 264; j += THREADS) {
            int i0 = l0 + 2 * j;
            float v0 = (i0     < L_IN) ? xb[i0]     : 0.0f;
            float v1 = (i0 + 1 < L_IN) ? xb[i0 + 1] : 0.0f;
            float v2 = (i0 + 2 < L_IN) ? xb[i0 + 2] : 0.0f;
            __nv_bfloat16 h0 = __float2bfloat16(v0);
            __nv_bfloat16 h1 = __float2bfloat16(v1);
            __nv_bfloat16 h2 = __float2bfloat16(v2);
            __nv_bfloat16 e0 = __float2bfloat16(v0 - __bfloat162float(h0));
            __nv_bfloat16 e1 = __float2bfloat16(v1 - __bfloat162float(h1));
            __nv_bfloat16 e2 = __float2bfloat16(v2 - __bfloat162float(h2));
            S->xeh[j] = pack_bf2(h0, h1);
            S->xoh[j] = pack_bf2(h1, h2);
            S->xel[j] = pack_bf2(e0, e1);
            S->xol[j] = pack_bf2(e1, e2);
        }
    }
    __syncthreads();

    const int rp = lane >> 2;       // row-in-group 0..7
    const int q  = lane & 3;
    const int p  = rp & 1;          // parity selects shifted copy
    const uint32_t* xh = p ? S->xoh : S->xeh;
    const uint32_t* xl = p ? S->xol : S->xel;
    int j0 = (w * 32 + rp + 2 * q) >> 1;    // word index, m-tile 0, kstep 0

    float D[2][NT][4];
    #pragma unroll
    for (int m = 0; m < 2; m++)
        #pragma unroll
        for (int n = 0; n < NT; n++)
            #pragma unroll
            for (int e = 0; e < 4; e++)
                D[m][n][e] = 0.0f;

    #pragma unroll 1
    for (int ks = 0; ks < KSTEPS; ks++) {
        uint32_t Ah[2][3], Al[2][3];
        #pragma unroll
        for (int m = 0; m < 2; m++) {
            int j = j0 + m * 8;
            Ah[m][0] = xh[j]; Ah[m][1] = xh[j + 4]; Ah[m][2] = xh[j + 8];
            Al[m][0] = xl[j]; Al[m][1] = xl[j + 4]; Al[m][2] = xl[j + 8];
        }
        #pragma unroll
        for (int n = 0; n < NT; n++) {
            uint2 bh = S->Hf[0][ks][n][lane];
            uint2 bl = S->Hf[1][ks][n][lane];
            #pragma unroll
            for (int m = 0; m < 2; m++) {
                // hh * xh
                mma16816(D[m][n], Ah[m][0], Ah[m][1], Ah[m][1], Ah[m][2], bh.x, bh.y);
                // hh * xl
                mma16816(D[m][n], Al[m][0], Al[m][1], Al[m][1], Al[m][2], bh.x, bh.y);
                // hl * xh
                mma16816(D[m][n], Ah[m][0], Ah[m][1], Ah[m][1], Ah[m][2], bl.x, bl.y);
            }
        }
        j0 += 8;
    }

    // ---- store: D[m][n] covers l = l0+32w+16m+rp (+8), f = 8n+2q (+1) ----
    float* ob = out + (size_t)b * N_FILT * L_OUT;
    #pragma unroll
    for (int m = 0; m < 2; m++) {
        int l = l0 + w * 32 + m * 16 + rp;
        #pragma unroll
        for (int n = 0; n < NT; n++) {
            int f = n * 8 + q * 2;
            if (l < L_OUT) {
                ob[(size_t)f * L_OUT + l]       = D[m][n][0];
                ob[(size_t)(f + 1) * L_OUT + l] = D[m][n][1];
            }
            if (l + 8 < L_OUT) {
                ob[(size_t)f * L_OUT + l + 8]       = D[m][n][2];
                ob[(size_t)(f + 1) * L_OUT + l + 8] = D[m][n][3];
            }
        }
    }
}

// ---------------------------------------------------------------------------
extern "C" void kernel_launch(void* const* d_in, const int* in_sizes, int n_in,
                              void* d_out, int out_size)
{
    const float* x       = (const float*)d_in[0];
    const float* norm_f1 = (const float*)d_in[1];
    const float* norm_f2 = (const float*)d_in[2];
    const float* ampl    = (const float*)d_in[3];
    float* out = (float*)d_out;

    cudaFuncSetAttribute(sinc_conv_kernel,
                         cudaFuncAttributeMaxDynamicSharedMemorySize,
                         (int)sizeof(Smem));

    build_filters_kernel<<<N_FILT, 128>>>(norm_f1, norm_f2, ampl);

    dim3 grid(NLT, BATCH);   // (125, 32)
    sinc_conv_kernel<<<grid, THREADS, sizeof(Smem)>>>(x, out);
}

// round 8
// speedup vs baseline: 2.5530x; 1.1161x over previous
#include <cuda_runtime.h>
#include <cuda_bf16.h>
#include <math.h>
#include <float.h>
#include <stdint.h>

#define FS        16000.0f
#define N_FILT    80
#define FILT_DIM  251
#define HALF_K    125
#define L_IN      32000
#define L_OUT     (L_IN - FILT_DIM + 1)   // 31750
#define BATCH     32

#define KF        128                      // folded K (126 used, padded)
#define KSTEPS    8                        // KF / 16
#define NT        10                       // 80 / 8 n-tiles
#define MTILE     128                      // l's per CTA (8 warps x 16 rows)
#define NLT       ((L_OUT + MTILE - 1) / MTILE)   // 249
#define THREADS   256
#define NWARP     8

// Folded H in fragment-linear layout: [split][kstep][ntile][lane] -> uint2
// b0 = (H'[f][16ks+2q], H'[f][16ks+2q+1]), b1 = same k+8; f = 8*nt + (lane>>2)
__device__ __align__(16) uint2 Hfrag_g[2][KSTEPS][NT][32];

struct Smem {
    uint4    Sh[NWARP][KSTEPS][32];   // A-fragments hi: 32768 B
    uint4    Sl[NWARP][KSTEPS][32];   // A-fragments lo: 32768 B
    uint2    Hf[2][KSTEPS][NT][32];   // 40960 B
    float    xraw[384];               // CTA x window
};

// ---------------------------------------------------------------------------
__device__ __forceinline__ uint32_t pack_bf2(__nv_bfloat16 a, __nv_bfloat16 b) {
    __nv_bfloat162 t; t.x = a; t.y = b;
    return *(uint32_t*)&t;
}

__device__ __forceinline__ void mma16816(float d[4],
                                         uint32_t a0, uint32_t a1,
                                         uint32_t a2, uint32_t a3,
                                         uint32_t b0, uint32_t b1) {
    asm volatile(
        "mma.sync.aligned.m16n8k16.row.col.f32.bf16.bf16.f32 "
        "{%0,%1,%2,%3}, {%4,%5,%6,%7}, {%8,%9}, {%0,%1,%2,%3};"
        : "+f"(d[0]), "+f"(d[1]), "+f"(d[2]), "+f"(d[3])
        : "r"(a0), "r"(a1), "r"(a2), "r"(a3), "r"(b0), "r"(b1));
}

// ---------------------------------------------------------------------------
// Kernel 1: build FOLDED taps (reference numerics; avg of the two window
// roundings per mirrored pair, validated at rel_err ~1e-6), split bf16 hi/lo,
// stored fragment-linear.
// ---------------------------------------------------------------------------
__global__ void build_filters_kernel(const float* __restrict__ norm_f1,
                                     const float* __restrict__ norm_f2,
                                     const float* __restrict__ amplitude)
{
    const int f = blockIdx.x;
    const int t = threadIdx.x;

    const float min_n = 50.0f / FS;
    float f1n = fabsf(norm_f1[f]) + min_n;
    float f2n = f1n + fabsf(norm_f2[f] - f1n) + min_n;
    float f1 = f1n * FS;
    float f2 = f2n * FS;
    float amp = fabsf(amplitude[f]);

    __shared__ float bp[HALF_K];
    __shared__ float red[128];

    const float TWO_PI = 6.283185307179586f;

    float v = -FLT_MAX;
    if (t < HALF_K) {
        float tr = (float)(t + 1) / FS;          // exact integers 1..125 / fs
        float a2 = TWO_PI * f2 * tr;             // fp32 arg like reference
        float a1 = TWO_PI * f1 * tr;
        float s2 = (float)(sin((double)a2) / (double)a2);
        float s1 = (float)(sin((double)a1) / (double)a1);
        float bb = amp * (2.0f * f2 * s2 - 2.0f * f1 * s1);
        bp[t] = bb;
        v = bb;
    }
    float center = amp * (2.0f * f2 - 2.0f * f1);
    v = fmaxf(v, center);

    red[t] = v;
    __syncthreads();
    for (int s = 64; s > 0; s >>= 1) {
        if (t < s) red[t] = fmaxf(red[t], red[t + s]);
        __syncthreads();
    }
    float mx = red[0];

    const int nt   = f >> 3;
    const int lrow = f & 7;

    for (int k = t; k < KF; k += blockDim.x) {
        float hv = 0.0f;
        if (k < HALF_K) {
            double wj  = 0.54 - 0.46 * cos(2.0 * M_PI * (double)k / 250.0);
            double wjm = 0.54 - 0.46 * cos(2.0 * M_PI * (double)(250 - k) / 250.0);
            hv = (bp[HALF_K - 1 - k] / mx) * (float)(0.5 * (wj + wjm));
        } else if (k == HALF_K) {
            hv = center / mx;                    // window = 1.0 at center
        }
        __nv_bfloat16 hi = __float2bfloat16(hv);
        __nv_bfloat16 lo = __float2bfloat16(hv - __bfloat162float(hi));

        int ks = k >> 4, kk = k & 15;
        int bsel = kk >> 3;            // b0 / b1
        int q    = (kk >> 1) & 3;      // thread-in-group
        int e    = kk & 1;             // element within b32
        int lane = lrow * 4 + q;

        ((__nv_bfloat16*)&Hfrag_g[0][ks][nt][lane])[bsel * 2 + e] = hi;
        ((__nv_bfloat16*)&Hfrag_g[1][ks][nt][lane])[bsel * 2 + e] = lo;
    }
}

// ---------------------------------------------------------------------------
// folded S element: r in [0,128), k in [0,128)
__device__ __forceinline__ float s_at(const float* __restrict__ xr, int r, int k) {
    if (k < HALF_K)  return xr[r + k] + xr[r + 250 - k];
    if (k == HALF_K) return xr[r + HALF_K];
    return 0.0f;
}

// ---------------------------------------------------------------------------
// Kernel 2: folded implicit-GEMM via mma.sync m16n8k16 bf16, 3-pass split.
// CTA: 1 batch x 128 l x 80 f. Warp w owns the m16-tile rows [16w, 16w+16).
// S (non-Toeplitz after folding) is materialized once into fragment-linear
// smem; each A fragment is then a single conflict-free LDS.128.
// ---------------------------------------------------------------------------
__global__ void __launch_bounds__(THREADS, 2)
sinc_conv_kernel(const float* __restrict__ x, float* __restrict__ out)
{
    extern __shared__ __align__(16) char smem_raw[];
    Smem* S = (Smem*)smem_raw;

    const int b    = blockIdx.y;
    const int l0   = blockIdx.x * MTILE;
    const int tid  = threadIdx.x;
    const int w    = tid >> 5;
    const int lane = tid & 31;

    // ---- stage H fragments (40 KB) ----
    {
        const uint4* src = (const uint4*)Hfrag_g;
        uint4* dst = (uint4*)S->Hf;
        #pragma unroll 5
        for (int i = tid; i < 2560; i += THREADS) dst[i] = src[i];
    }
    // ---- stage raw x window ----
    {
        const float* xb = x + (size_t)b * L_IN;
        for (int i = tid; i < 384; i += THREADS) {
            int gi = l0 + i;
            S->xraw[i] = (gi < L_IN) ? xb[gi] : 0.0f;
        }
    }
    __syncthreads();

    // ---- materialize folded S fragments (hi/lo bf16) ----
    {
        const float* xr = S->xraw;
        for (int idx = tid; idx < NWARP * KSTEPS * 32; idx += THREADS) {
            int ln  = idx & 31;
            int ks  = (idx >> 5) & 7;
            int w2  = idx >> 8;
            int gid = ln >> 2;        // row-in-group
            int tig = ln & 3;         // k-pair index
            int r0  = 16 * w2 + gid;
            int k0  = 16 * ks + 2 * tig;

            float e0 = s_at(xr, r0,     k0);
            float e1 = s_at(xr, r0,     k0 + 1);
            float e2 = s_at(xr, r0 + 8, k0);
            float e3 = s_at(xr, r0 + 8, k0 + 1);
            float e4 = s_at(xr, r0,     k0 + 8);
            float e5 = s_at(xr, r0,     k0 + 9);
            float e6 = s_at(xr, r0 + 8, k0 + 8);
            float e7 = s_at(xr, r0 + 8, k0 + 9);

            __nv_bfloat16 h0 = __float2bfloat16(e0), h1 = __float2bfloat16(e1);
            __nv_bfloat16 h2 = __float2bfloat16(e2), h3 = __float2bfloat16(e3);
            __nv_bfloat16 h4 = __float2bfloat16(e4), h5 = __float2bfloat16(e5);
            __nv_bfloat16 h6 = __float2bfloat16(e6), h7 = __float2bfloat16(e7);

            uint4 hv, lv;
            hv.x = pack_bf2(h0, h1);                       // a0: (r, k), (r, k+1)
            hv.y = pack_bf2(h2, h3);                       // a1: rows +8
            hv.z = pack_bf2(h4, h5);                       // a2: cols +8
            hv.w = pack_bf2(h6, h7);                       // a3: rows+8, cols+8
            lv.x = pack_bf2(__float2bfloat16(e0 - __bfloat162float(h0)),
                            __float2bfloat16(e1 - __bfloat162float(h1)));
            lv.y = pack_bf2(__float2bfloat16(e2 - __bfloat162float(h2)),
                            __float2bfloat16(e3 - __bfloat162float(h3)));
            lv.z = pack_bf2(__float2bfloat16(e4 - __bfloat162float(h4)),
                            __float2bfloat16(e5 - __bfloat162float(h5)));
            lv.w = pack_bf2(__float2bfloat16(e6 - __bfloat162float(h6)),
                            __float2bfloat16(e7 - __bfloat162float(h7)));

            S->Sh[w2][ks][ln] = hv;
            S->Sl[w2][ks][ln] = lv;
        }
    }
    __syncthreads();

    float D[NT][4];
    #pragma unroll
    for (int n = 0; n < NT; n++)
        #pragma unroll
        for (int e = 0; e < 4; e++)
            D[n][e] = 0.0f;

    #pragma unroll 2
    for (int ks = 0; ks < KSTEPS; ks++) {
        uint4 Ah = S->Sh[w][ks][lane];
        uint4 Al = S->Sl[w][ks][lane];
        #pragma unroll
        for (int n = 0; n < NT; n++) {
            uint2 bh = S->Hf[0][ks][n][lane];
            uint2 bl = S->Hf[1][ks][n][lane];
            mma16816(D[n], Ah.x, Ah.y, Ah.z, Ah.w, bh.x, bh.y);  // hh * sh
            mma16816(D[n], Al.x, Al.y, Al.z, Al.w, bh.x, bh.y);  // hh * sl
            mma16816(D[n], Ah.x, Ah.y, Ah.z, Ah.w, bl.x, bl.y);  // hl * sh
        }
    }

    // ---- store: D[n] covers l = l0+16w+rp (+8), f = 8n+2q (+1) ----
    const int rp = lane >> 2;
    const int q  = lane & 3;
    const int l  = l0 + 16 * w + rp;
    float* ob = out + (size_t)b * N_FILT * L_OUT;
    #pragma unroll
    for (int n = 0; n < NT; n++) {
        int f = n * 8 + q * 2;
        if (l < L_OUT) {
            ob[(size_t)f * L_OUT + l]       = D[n][0];
            ob[(size_t)(f + 1) * L_OUT + l] = D[n][1];
        }
        if (l + 8 < L_OUT) {
            ob[(size_t)f * L_OUT + l + 8]       = D[n][2];
            ob[(size_t)(f + 1) * L_OUT + l + 8] = D[n][3];
        }
    }
}

// ---------------------------------------------------------------------------
extern "C" void kernel_launch(void* const* d_in, const int* in_sizes, int n_in,
                              void* d_out, int out_size)
{
    const float* x       = (const float*)d_in[0];
    const float* norm_f1 = (const float*)d_in[1];
    const float* norm_f2 = (const float*)d_in[2];
    const float* ampl    = (const float*)d_in[3];
    float* out = (float*)d_out;

    cudaFuncSetAttribute(sinc_conv_kernel,
                         cudaFuncAttributeMaxDynamicSharedMemorySize,
                         (int)sizeof(Smem));

    build_filters_kernel<<<N_FILT, 128>>>(norm_f1, norm_f2, ampl);

    dim3 grid(NLT, BATCH);   // (249, 32)
    sinc_conv_kernel<<<grid, THREADS, sizeof(Smem)>>>(x, out);
}